// round 17
// baseline (speedup 1.0000x reference)
#include <cuda_runtime.h>
#include <cstdint>

#define B 8
#define L 512
#define H 20
#define D 1280
#define K 32

#define K1_BLOCKS     148   // 16 topk + 1 bias + padding (>=148: no throttle)
#define MATVEC_BLOCKS 320   // 16 warps * 320 = 5120 half-rows = 2*2560 rows
#define K2_BLOCKS     (MATVEC_BLOCKS + 16)   // + 16 gather-sum blocks
#define K3_BLOCKS     148   // 8 working + padding

// Scratch (no allocations allowed in kernel_launch)
__device__ int   g_idx[2][B][K];    // top-K token indices per (rep, batch)
__device__ float g_up[2][4][D];     // j-half partials of u1,u2,v1,v2
__device__ float g_s[2][B][D];      // gather-SUM of selected rep rows
__device__ float g_bias;            // batch-independent bias dot

// ---------------------------------------------------------------------------
// Warp-register bitonic sort, 32 u64 keys across lanes, DESCENDING.
// ---------------------------------------------------------------------------
__device__ __forceinline__ unsigned long long warp_sort_desc(
    unsigned long long key, int lane)
{
    unsigned long long v = ~key;
#pragma unroll
    for (int k = 2; k <= 32; k <<= 1) {
#pragma unroll
        for (int j = k >> 1; j > 0; j >>= 1) {
            unsigned long long other = __shfl_xor_sync(0xffffffffu, v, j);
            bool lower = (lane & j) == 0;
            bool up    = (lane & k) == 0;
            unsigned long long mn = (v < other) ? v : other;
            unsigned long long mx = (v < other) ? other : v;
            v = (lower == up) ? mn : mx;
        }
    }
    return ~v;   // lane i holds i-th LARGEST original key
}

// ---------------------------------------------------------------------------
// Kernel 1: grid 148. [0,16): top-K per (rep,batch); 16: bias dot; rest exit.
// ---------------------------------------------------------------------------
__global__ void __launch_bounds__(512) k_topk(
    const float* __restrict__ attn1, const float* __restrict__ attn2,
    const int* __restrict__ pos,
    const float* __restrict__ cls_b, const float* __restrict__ env_b,
    const float* __restrict__ clsclf_W, const float* __restrict__ envclf_W,
    const float* __restrict__ cls_c1, const float* __restrict__ cls_c2,
    const float* __restrict__ env_c1, const float* __restrict__ env_c2)
{
    const int warp = threadIdx.x >> 5;
    const int lane = threadIdx.x & 31;

    if (blockIdx.x == 16) {
        // --- bias dot (one warp) ---
        if (warp != 0) return;
        float a = 0.f;
        for (int d = lane; d < D; d += 32)
            a += cls_b[d] * (cls_c1[d] + cls_c2[d]) * clsclf_W[d]
               + env_b[d] * (env_c1[d] + env_c2[d]) * envclf_W[d];
#pragma unroll
        for (int o = 16; o; o >>= 1)
            a += __shfl_xor_sync(0xffffffffu, a, o);
        if (lane == 0) g_bias = a;
        return;
    }
    if (blockIdx.x > 16) return;   // padding blocks

    // --- top-K for one (rep, batch) ---
    const int tb = blockIdx.x;                   // 0..15
    const int b  = tb & 7;
    const int r  = tb >> 3;
    const float* attn = r ? attn2 : attn1;
    const int l = threadIdx.x;                   // token 0..511
    const int p = pos[b];

    const float* base = attn + ((size_t)b * H) * (size_t)(L * L)
                             + (size_t)p * L + l;
    float s = 0.f;
#pragma unroll
    for (int h = 0; h < H; ++h)
        s += base[(size_t)h * (L * L)];

    unsigned fb = __float_as_uint(s * (1.0f / H));
    fb = (fb & 0x80000000u) ? ~fb : (fb | 0x80000000u);
    unsigned long long key =
        ((unsigned long long)fb << 32) | (unsigned)(L - 1 - l);

    key = warp_sort_desc(key, lane);

    __shared__ unsigned long long sorted[16][32];
    sorted[warp][lane] = key;
    __syncthreads();

    if (warp == 0) {
        unsigned long long h = (lane < 16) ? sorted[lane][0] : 0ull;
        int ptr = 0;
#pragma unroll
        for (int i = 0; i < K; ++i) {
            unsigned long long m = h;
#pragma unroll
            for (int o = 8; o; o >>= 1) {
                unsigned long long other = __shfl_xor_sync(0xffffffffu, m, o);
                if (other > m) m = other;
            }
            m = __shfl_sync(0xffffffffu, m, 0);
            if (h == m) {
                g_idx[r][b][i] = L - 1 - (int)(m & 0xffffffffu);
                ++ptr;
                h = (ptr < 32) ? sorted[lane][ptr] : 0ull;
            }
        }
    }
}

// ---------------------------------------------------------------------------
// Kernel 2: grid 336.
//   [0,320):   dual matvec half-rows (BYTE-IDENTICAL to the 14.8us version)
//   [320,336): gather-sum for one (rep,batch): g_idx is ready (kernel
//              boundary) -> no wait; 2.6MB streams concurrently with W.
// ---------------------------------------------------------------------------
__global__ void __launch_bounds__(512) k_main(
    const float* __restrict__ rep1, const float* __restrict__ rep2,
    const float* __restrict__ cls_W, const float* __restrict__ env_W,
    const float* __restrict__ clsclf_W, const float* __restrict__ envclf_W,
    const float* __restrict__ cls_c1, const float* __restrict__ cls_c2,
    const float* __restrict__ env_c1, const float* __restrict__ env_c2)
{
    const int warp = threadIdx.x >> 5;
    const int lane = threadIdx.x & 31;

    if (blockIdx.x < MATVEC_BLOCKS) {
        const int gw   = blockIdx.x * 16 + warp;   // 0..5119
        const int half = gw & 1;
        const int grow = gw >> 1;                  // 0..2559
        const int mat  = grow >= D;
        const int row  = grow - mat * D;
        const float* W  = mat ? env_W    : cls_W;
        const float* wc = mat ? envclf_W : clsclf_W;
        const float* c1 = mat ? env_c1   : cls_c1;
        const float* c2 = mat ? env_c2   : cls_c2;
        const float* Wr = W + (size_t)row * D;
        const int j0 = half * (D / 2) + lane * 4;

        float4 wv[5];
#pragma unroll
        for (int it = 0; it < 5; ++it)
            wv[it] = *(const float4*)(Wr + j0 + it * 128);

        float a1 = 0.f, a2 = 0.f;
#pragma unroll
        for (int it = 0; it < 5; ++it) {
            const int j = j0 + it * 128;
            float4 wcv = *(const float4*)(wc + j);
            float4 c1v = *(const float4*)(c1 + j);
            float4 c2v = *(const float4*)(c2 + j);
            float sx = wv[it].x * wcv.x, sy = wv[it].y * wcv.y,
                  sz = wv[it].z * wcv.z, sw = wv[it].w * wcv.w;
            a1 += sx * c1v.x + sy * c1v.y + sz * c1v.z + sw * c1v.w;
            a2 += sx * c2v.x + sy * c2v.y + sz * c2v.z + sw * c2v.w;
        }
#pragma unroll
        for (int o = 16; o; o >>= 1) {
            a1 += __shfl_xor_sync(0xffffffffu, a1, o);
            a2 += __shfl_xor_sync(0xffffffffu, a2, o);
        }
        if (lane == 0) {
            g_up[half][mat * 2 + 0][row] = a1;
            g_up[half][mat * 2 + 1][row] = a2;
        }
        return;
    }

    // ---- gather-sum for one (rep, batch): no wait needed -------------------
    const int tb = blockIdx.x - MATVEC_BLOCKS;   // 0..15
    const int b  = tb & 7;
    const int r  = tb >> 3;
    const float* rep  = r ? rep2 : rep1;
    const float* repb = rep + (size_t)b * L * D;
    const int tid = threadIdx.x;

    const int myrow = g_idx[r][b][lane];
    float a0 = 0.f, a1 = 0.f, a2 = 0.f;
#pragma unroll
    for (int t = 0; t < K; ++t) {
        const int row = __shfl_sync(0xffffffffu, myrow, t);
        const float* rp = repb + (size_t)row * D;
        a0 += rp[tid];
        a1 += rp[tid + 512];
        if (tid < 256) a2 += rp[tid + 1024];
    }
    g_s[r][b][tid]       = a0;
    g_s[r][b][tid + 512] = a1;
    if (tid < 256) g_s[r][b][tid + 1024] = a2;
}

// ---------------------------------------------------------------------------
// Kernel 3: grid 148; blocks [0,8) work (one per batch), rest exit.
// Block b: cls dot (token-0 rows vs u1,u2) + env dot (g_s vs v1,v2),
// block-reduce, write out[b] directly. No atomics, no drain.
// ---------------------------------------------------------------------------
__global__ void __launch_bounds__(512) k_final(
    const float* __restrict__ rep1, const float* __restrict__ rep2,
    const float* __restrict__ clsclf_b, const float* __restrict__ envclf_b,
    float* __restrict__ out)
{
    if (blockIdx.x >= B) return;

    const int b    = blockIdx.x;
    const int tid  = threadIdx.x;
    const int warp = tid >> 5;
    const int lane = tid & 31;

    const float* r1 = rep1 + (size_t)b * L * D;   // token-0 rows
    const float* r2 = rep2 + (size_t)b * L * D;

    float cls = 0.f, env = 0.f;
#pragma unroll
    for (int base = 0; base < D; base += 512) {
        const int d = base + tid;
        if (d < D) {
            cls += r1[d] * (g_up[0][0][d] + g_up[1][0][d])
                 + r2[d] * (g_up[0][1][d] + g_up[1][1][d]);
            env += g_s[0][b][d] * (g_up[0][2][d] + g_up[1][2][d])
                 + g_s[1][b][d] * (g_up[0][3][d] + g_up[1][3][d]);
        }
    }

    __shared__ float redc[16], rede[16];
#pragma unroll
    for (int o = 16; o; o >>= 1) {
        cls += __shfl_xor_sync(0xffffffffu, cls, o);
        env += __shfl_xor_sync(0xffffffffu, env, o);
    }
    if (lane == 0) { redc[warp] = cls; rede[warp] = env; }
    __syncthreads();

    if (tid == 0) {
        float c = 0.f, e = 0.f;
#pragma unroll
        for (int w = 0; w < 16; ++w) { c += redc[w]; e += rede[w]; }
        out[b] = (c + e * (1.0f / K)
                  + g_bias + clsclf_b[0] + envclf_b[0]) * 0.5f;
    }
}

// ---------------------------------------------------------------------------
extern "C" void kernel_launch(void* const* d_in, const int* in_sizes, int n_in,
                              void* d_out, int out_size)
{
    const float* rep1     = (const float*)d_in[0];
    const float* rep2     = (const float*)d_in[1];
    const float* attn1    = (const float*)d_in[2];
    const float* attn2    = (const float*)d_in[3];
    const int*   pos      = (const int*)  d_in[4];
    const float* cls_W    = (const float*)d_in[5];
    const float* cls_b    = (const float*)d_in[6];
    const float* env_W    = (const float*)d_in[7];
    const float* env_b    = (const float*)d_in[8];
    const float* clsclf_W = (const float*)d_in[9];
    const float* clsclf_b = (const float*)d_in[10];
    const float* envclf_W = (const float*)d_in[11];
    const float* envclf_b = (const float*)d_in[12];
    const float* cls_c1   = (const float*)d_in[13];
    const float* cls_c2   = (const float*)d_in[14];
    const float* env_c1   = (const float*)d_in[15];
    const float* env_c2   = (const float*)d_in[16];
    float* out = (float*)d_out;

    k_topk<<<K1_BLOCKS, 512>>>(attn1, attn2, pos, cls_b, env_b,
                               clsclf_W, envclf_W,
                               cls_c1, cls_c2, env_c1, env_c2);

    k_main<<<K2_BLOCKS, 512>>>(rep1, rep2, cls_W, env_W,
                               clsclf_W, envclf_W,
                               cls_c1, cls_c2, env_c1, env_c2);

    k_final<<<K3_BLOCKS, 512>>>(rep1, rep2, clsclf_b, envclf_b, out);
}